// round 11
// baseline (speedup 1.0000x reference)
#include <cuda_runtime.h>
#include <cuda_bf16.h>
#include <math.h>
#include <stdint.h>

#define MAXN 20000
#define MAXE 320000

// ---------------- device scratch (no allocs allowed) ----------------
__device__ int   g_is64;
__device__ int   g_src[MAXE];
__device__ int   g_dst[MAXE];
__device__ int   g_esrc[MAXE];
__device__ float g_ewn[MAXE];
__device__ float g_deg[MAXN];
__device__ float g_dinv[MAXN];
__device__ int   g_cnt[MAXN];
__device__ int   g_rowptr[MAXN + 1];
__device__ int   g_cursor[MAXN];
__device__ int   g_part[32];
__device__ int   g_off2[32];
__device__ int   g_total;
__device__ float g_base[(long long)MAXN * 512];   // permuted gate layout [r][P], P = hcol*4 + gate
__device__ float g_h[MAXN * 128];
__device__ float g_c[MAXN * 128];
// bf16-split activations
__device__ __nv_bfloat16 g_Ph[MAXN * 256];   // [P_h | P_c] hi
__device__ __nv_bfloat16 g_Pl[MAXN * 256];   // lo
__device__ __nv_bfloat16 g_zh[MAXN * 128];
__device__ __nv_bfloat16 g_zl[MAXN * 128];
// bf16-split transposed weights, perm P = hcol*4 + gate
__device__ __nv_bfloat16 g_WTh[2 * 512 * 128];
__device__ __nv_bfloat16 g_WTl[2 * 512 * 128];
__device__ __nv_bfloat16 g_WIh[256 * 256];
__device__ __nv_bfloat16 g_WIl[256 * 256];
// fp32 permuted W_cell m=1 half, [k][P] row-major (for f32x2 role)
__device__ float g_Wp[128 * 512];

// ---------------- helpers ----------------
__device__ __forceinline__ float tanhA(float x) {
    float r; asm("tanh.approx.f32 %0, %1;" : "=f"(r) : "f"(x)); return r;
}
__device__ __forceinline__ float sigA(float x) {
    return fmaf(tanhA(0.5f * x), 0.5f, 0.5f);
}
__device__ __forceinline__ uint32_t smem_u32(const void* p) {
    uint32_t a;
    asm("{ .reg .u64 t; cvta.to.shared.u64 t, %1; cvt.u32.u64 %0, t; }" : "=r"(a) : "l"(p));
    return a;
}

#define FMA2(a, x, w) asm("fma.rn.f32x2 %0, %1, %2, %0;" : "+l"(a) : "l"(x), "l"(w))
__device__ __forceinline__ unsigned long long pk2(float v) {
    unsigned long long r;
    asm("mov.b64 %0, {%1, %1};" : "=l"(r) : "f"(v));
    return r;
}
__device__ __forceinline__ void upk2(float& lo, float& hi, unsigned long long v) {
    asm("mov.b64 {%0, %1}, %2;" : "=f"(lo), "=f"(hi) : "l"(v));
}

#define CP16(dst, src, srcsz) \
    asm volatile("cp.async.ca.shared.global [%0], [%1], 16, %2;" \
        :: "r"(dst), "l"(src), "r"(srcsz))
#define CP_COMMIT() asm volatile("cp.async.commit_group;" ::: "memory")
#define CP_WAIT(nn) asm volatile("cp.async.wait_group %0;" :: "n"(nn) : "memory")

#define LDSM4(r0, r1, r2, r3, a) \
    asm volatile("ldmatrix.sync.aligned.m8n8.x4.shared.b16 {%0,%1,%2,%3}, [%4];" \
        : "=r"(r0), "=r"(r1), "=r"(r2), "=r"(r3) : "r"(a))

#define MMA16816(d, a0, a1, a2, a3, b0, b1) \
    asm volatile("mma.sync.aligned.m16n8k16.row.col.f32.bf16.bf16.f32 " \
        "{%0,%1,%2,%3}, {%4,%5,%6,%7}, {%8,%9}, {%0,%1,%2,%3};" \
        : "+f"((d)[0]), "+f"((d)[1]), "+f"((d)[2]), "+f"((d)[3]) \
        : "r"(a0), "r"(a1), "r"(a2), "r"(a3), "r"(b0), "r"(b1))

// smem swizzle: 64B rows, 4x16B granules, conflict-free for 8-row LDSM phases
__device__ __forceinline__ uint32_t swz(int row, int g) {
    return (uint32_t)(row * 64 + ((g ^ ((row >> 1) & 3)) << 4));
}

// ---------------- setup kernels ----------------
__global__ void k_init(int n) {
    int i = blockIdx.x * blockDim.x + threadIdx.x;
    if (i < n) { g_deg[i] = 0.f; g_cnt[i] = 0; }
    if (i == 0) g_is64 = 1;
}

__global__ void k_detect(const unsigned int* __restrict__ w) {
    unsigned int v = w[2 * threadIdx.x + 1];
    if (v != 0u) g_is64 = 0;
}

__global__ void k_build(const void* __restrict__ ei, const float* __restrict__ ea, int E) {
    int e = blockIdx.x * blockDim.x + threadIdx.x;
    if (e >= E) return;
    int s, d;
    if (g_is64) {
        const long long* p = (const long long*)ei;
        s = (int)p[e]; d = (int)p[E + e];
    } else {
        const int* p = (const int*)ei;
        s = p[e]; d = p[E + e];
    }
    g_src[e] = s; g_dst[e] = d;
    atomicAdd(&g_deg[d], ea[e]);
    atomicAdd(&g_cnt[d], 1);
}

// hierarchical scan pass 1 (+ dinv fused)
__global__ void k_scan1(int n) {
    __shared__ int s[1024];
    int i = blockIdx.x * 1024 + threadIdx.x;
    if (i < n) g_dinv[i] = rsqrtf(g_deg[i] + 1.0f);
    int v = (i < n) ? g_cnt[i] : 0;
    s[threadIdx.x] = v;
    __syncthreads();
    for (int off = 1; off < 1024; off <<= 1) {
        int t = (threadIdx.x >= off) ? s[threadIdx.x - off] : 0;
        __syncthreads();
        s[threadIdx.x] += t;
        __syncthreads();
    }
    if (i < n) g_rowptr[i] = s[threadIdx.x] - v;   // local exclusive
    if (threadIdx.x == 1023) g_part[blockIdx.x] = s[1023];
}

__global__ void k_scan2(int nb) {
    int tid = threadIdx.x;                 // 32 threads
    int v = (tid < nb) ? g_part[tid] : 0;
    int incl = v;
    for (int o = 1; o < 32; o <<= 1) {
        int t = __shfl_up_sync(0xffffffffu, incl, o);
        if (tid >= o) incl += t;
    }
    if (tid < nb) g_off2[tid] = incl - v;
    if (tid == 31) g_total = incl;
}

__global__ void k_scan3(int n) {
    int i = blockIdx.x * 1024 + threadIdx.x;
    if (i < n) {
        int val = g_rowptr[i] + g_off2[blockIdx.x];
        g_rowptr[i] = val;
        g_cursor[i] = val;
    }
    if (i == 0) g_rowptr[n] = g_total;
}

__global__ void k_scatter(const float* __restrict__ ea, int E) {
    int e = blockIdx.x * blockDim.x + threadIdx.x;
    if (e >= E) return;
    int s = g_src[e], d = g_dst[e];
    int pos = atomicAdd(&g_cursor[d], 1);
    g_esrc[pos] = s;
    g_ewn[pos] = g_dinv[s] * ea[e] * g_dinv[d];
}

// fused weight transpose + permute + splits
// ids [0, 131072): W_cell bf16 split; perm P = hcol*4 + q <-> orig col q*128 + hcol
// ids [131072, 196608): W_init bf16 split, transposed [p][k]
// ids [196608, 262144): g_Wp fp32 permuted copy [k][P] of W_cell m=1 half
__global__ void k_split(const float* __restrict__ Wc, const float* __restrict__ Wi) {
    int id = blockIdx.x * blockDim.x + threadIdx.x;   // 0 .. 262143
    if (id < 131072) {
        int m = id >> 16;
        int rem = id & 65535;
        int p = rem >> 7;
        int k = rem & 127;
        int hcol = p >> 2, q = p & 3;
        int nc = q * 128 + hcol;
        float v = Wc[(long long)(m * 128 + k) * 512 + nc];
        __nv_bfloat16 hb = __float2bfloat16_rn(v);
        float lf = v - __bfloat162float(hb);
        g_WTh[id] = hb;
        g_WTl[id] = __float2bfloat16_rn(lf);
    } else if (id < 196608) {
        int id2 = id - 131072;
        int p = id2 >> 8;
        int k = id2 & 255;
        float v = Wi[(long long)k * 256 + p];
        __nv_bfloat16 hb = __float2bfloat16_rn(v);
        float lf = v - __bfloat162float(hb);
        g_WIh[id2] = hb;
        g_WIl[id2] = __float2bfloat16_rn(lf);
    } else {
        int id3 = id - 196608;
        int k = id3 >> 9;
        int P = id3 & 511;
        int hcol = P >> 2, q = P & 3;
        g_Wp[id3] = Wc[(long long)(128 + k) * 512 + q * 128 + hcol];
    }
}

// ---------------- sparse propagate -> bf16 hi/lo split output ----------------
__global__ void k_prop(const float* __restrict__ x0, const float* __restrict__ x1,
                       __nv_bfloat16* __restrict__ oh, __nv_bfloat16* __restrict__ ol,
                       int ldo, int n) {
    const float* x = blockIdx.y ? x1 : x0;
    int coff = blockIdx.y * 128;
    int v = (blockIdx.x * blockDim.x + threadIdx.x) >> 5;
    int lane = threadIdx.x & 31;
    if (v >= n) return;
    int beg = g_rowptr[v], end = g_rowptr[v + 1];
    float ax = 0.f, ay = 0.f, az = 0.f, aw = 0.f;
    int e = beg;
    for (; e + 1 < end; e += 2) {
        int s0 = g_esrc[e], s1 = g_esrc[e + 1];
        float w0 = g_ewn[e], w1 = g_ewn[e + 1];
        float4 v0 = __ldg((const float4*)(x + (long long)s0 * 128) + lane);
        float4 v1 = __ldg((const float4*)(x + (long long)s1 * 128) + lane);
        ax = fmaf(w0, v0.x, ax); ay = fmaf(w0, v0.y, ay);
        az = fmaf(w0, v0.z, az); aw = fmaf(w0, v0.w, aw);
        ax = fmaf(w1, v1.x, ax); ay = fmaf(w1, v1.y, ay);
        az = fmaf(w1, v1.z, az); aw = fmaf(w1, v1.w, aw);
    }
    if (e < end) {
        int s0 = g_esrc[e];
        float w0 = g_ewn[e];
        float4 v0 = __ldg((const float4*)(x + (long long)s0 * 128) + lane);
        ax = fmaf(w0, v0.x, ax); ay = fmaf(w0, v0.y, ay);
        az = fmaf(w0, v0.z, az); aw = fmaf(w0, v0.w, aw);
    }
    float di = g_dinv[v];
    float w2 = di * di;
    float4 vv = __ldg((const float4*)(x + (long long)v * 128) + lane);
    ax = fmaf(w2, vv.x, ax); ay = fmaf(w2, vv.y, ay);
    az = fmaf(w2, vv.z, az); aw = fmaf(w2, vv.w, aw);
    float a[4] = {ax, ay, az, aw};
    unsigned short hs[4], ls[4];
#pragma unroll
    for (int m = 0; m < 4; m++) {
        __nv_bfloat16 hb = __float2bfloat16_rn(a[m]);
        float lf = a[m] - __bfloat162float(hb);
        __nv_bfloat16 lb = __float2bfloat16_rn(lf);
        hs[m] = *(unsigned short*)&hb;
        ls[m] = *(unsigned short*)&lb;
    }
    *(uint2*)(oh + (long long)v * ldo + coff + lane * 4) = *(uint2*)hs;
    *(uint2*)(ol + (long long)v * ldo + coff + lane * 4) = *(uint2*)ls;
}

// ---------------- heterogeneous sequence kernel ----------------
// CTAs [0, NSM): persistent HMMA workers, loop over jobs = (mtile, y) for rows [0, n1)
// CTAs [NSM, ...): f32x2 CTAs, 64 rows x 256 permuted cols each, rows [n1, n)
// Both: gates = D + base_perm; LSTM update of g_c; write oseq.
__global__ void __launch_bounds__(256, 2)
k_seq(const float* __restrict__ baseb, float* __restrict__ oseq,
      int n, int n1, int mt1, int NSM) {
    extern __shared__ char sm[];
    const uint32_t sb = smem_u32(sm);
    const int tid = threadIdx.x;
    const int lane = tid & 31;
    const int wid = tid >> 5;
    const int bid = blockIdx.x;

    if (bid < NSM) {
        // ================= HMMA role =================
        const __nv_bfloat16* Ah = g_zh;
        const __nv_bfloat16* Al = g_zl;
        const __nv_bfloat16* Bh = g_WTh + 512 * 128;
        const __nv_bfloat16* Bl = g_WTl + 512 * 128;
        const int mw = (wid & 3) * 32;
        const int nw = (wid >> 2) * 64;
        const int njobs = mt1 * 4;

        for (int job = bid; job < njobs; job += NSM) {
            const int m0 = (job >> 2) * 128;
            const int t = job & 3;

            float acc[2][8][4];
#pragma unroll
            for (int i = 0; i < 2; i++)
#pragma unroll
                for (int j = 0; j < 8; j++)
#pragma unroll
                    for (int q = 0; q < 4; q++) acc[i][j][q] = 0.f;

            auto stage = [&](int ks) {
                uint32_t bufo = (uint32_t)(ks % 3) * 32768;
#pragma unroll
                for (int it = 0; it < 8; it++) {
                    int id = tid + it * 256;
                    int arr = id >> 9;
                    int rem = id & 511;
                    int row = rem >> 2, g = rem & 3;
                    uint32_t dst = sb + bufo + arr * 8192 + swz(row, g);
                    if (arr < 2) {
                        const __nv_bfloat16* src = (arr == 0 ? Ah : Al)
                            + (size_t)(m0 + row) * 128 + ks * 32 + g * 8;
                        CP16(dst, src, 16);
                    } else {
                        const __nv_bfloat16* src = (arr == 2 ? Bh : Bl)
                            + (size_t)(t * 128 + row) * 128 + ks * 32 + g * 8;
                        CP16(dst, src, 16);
                    }
                }
                CP_COMMIT();
            };

            stage(0);
            stage(1);
#pragma unroll
            for (int ks = 0; ks < 4; ks++) {
                if (ks == 3) { CP_WAIT(0); } else { CP_WAIT(1); }
                __syncthreads();
                if (ks + 2 < 4) stage(ks + 2);
                uint32_t abase = sb + (uint32_t)(ks % 3) * 32768;
                uint32_t bbase = abase + 16384;
#pragma unroll
                for (int kc = 0; kc < 2; kc++) {
                    uint32_t ah[2][4], al[2][4];
#pragma unroll
                    for (int mf = 0; mf < 2; mf++) {
                        int row = mw + mf * 16 + (lane & 15);
                        int g = kc * 2 + (lane >> 4);
                        uint32_t a = abase + swz(row, g);
                        LDSM4(ah[mf][0], ah[mf][1], ah[mf][2], ah[mf][3], a);
                        LDSM4(al[mf][0], al[mf][1], al[mf][2], al[mf][3], a + 8192);
                    }
#pragma unroll
                    for (int bp = 0; bp < 4; bp++) {
                        int p = nw + bp * 16 + ((lane >> 4) << 3) + (lane & 7);
                        int g = kc * 2 + ((lane >> 3) & 1);
                        uint32_t a = bbase + swz(p, g);
                        uint32_t h0, h1, h2, h3, l0, l1, l2, l3;
                        LDSM4(h0, h1, h2, h3, a);
                        LDSM4(l0, l1, l2, l3, a + 8192);
                        MMA16816(acc[0][2 * bp],     ah[0][0], ah[0][1], ah[0][2], ah[0][3], h0, h1);
                        MMA16816(acc[1][2 * bp],     ah[1][0], ah[1][1], ah[1][2], ah[1][3], h0, h1);
                        MMA16816(acc[0][2 * bp + 1], ah[0][0], ah[0][1], ah[0][2], ah[0][3], h2, h3);
                        MMA16816(acc[1][2 * bp + 1], ah[1][0], ah[1][1], ah[1][2], ah[1][3], h2, h3);
                        MMA16816(acc[0][2 * bp],     ah[0][0], ah[0][1], ah[0][2], ah[0][3], l0, l1);
                        MMA16816(acc[1][2 * bp],     ah[1][0], ah[1][1], ah[1][2], ah[1][3], l0, l1);
                        MMA16816(acc[0][2 * bp + 1], ah[0][0], ah[0][1], ah[0][2], ah[0][3], l2, l3);
                        MMA16816(acc[1][2 * bp + 1], ah[1][0], ah[1][1], ah[1][2], ah[1][3], l2, l3);
                        MMA16816(acc[0][2 * bp],     al[0][0], al[0][1], al[0][2], al[0][3], h0, h1);
                        MMA16816(acc[1][2 * bp],     al[1][0], al[1][1], al[1][2], al[1][3], h0, h1);
                        MMA16816(acc[0][2 * bp + 1], al[0][0], al[0][1], al[0][2], al[0][3], h2, h3);
                        MMA16816(acc[1][2 * bp + 1], al[1][0], al[1][1], al[1][2], al[1][3], h2, h3);
                    }
                }
            }

            // epilogue (rows all < n1 <= n)
#pragma unroll
            for (int mf = 0; mf < 2; mf++) {
                int r0 = m0 + mw + mf * 16 + (lane >> 2);
                int r1 = r0 + 8;
#pragma unroll
                for (int nf = 0; nf < 8; nf++) {
                    float d0 = acc[mf][nf][0], d1 = acc[mf][nf][1];
                    float d2 = acc[mf][nf][2], d3 = acc[mf][nf][3];
                    int c0 = nw + nf * 8 + (lane & 3) * 2;
                    int P0 = t * 128 + c0;
                    float2 b0 = *(const float2*)(baseb + (size_t)r0 * 512 + P0);
                    float2 b1 = *(const float2*)(baseb + (size_t)r1 * 512 + P0);
                    float v0 = d0 + b0.x, v1 = d1 + b0.y;
                    float v2 = d2 + b1.x, v3 = d3 + b1.y;
                    float u0 = __shfl_xor_sync(0xffffffffu, v0, 1);
                    float u1 = __shfl_xor_sync(0xffffffffu, v1, 1);
                    float u2 = __shfl_xor_sync(0xffffffffu, v2, 1);
                    float u3 = __shfl_xor_sync(0xffffffffu, v3, 1);
                    if (!(lane & 1)) {
                        int hcol = P0 >> 2;
                        size_t ix0 = (size_t)r0 * 128 + hcol;
                        float c0ld = g_c[ix0];
                        float cn0 = sigA(v1) * c0ld + sigA(v0) * tanhA(u1);
                        float hn0 = sigA(u0) * tanhA(cn0);
                        g_c[ix0] = cn0; oseq[ix0] = hn0;
                        size_t ix1 = (size_t)r1 * 128 + hcol;
                        float c1ld = g_c[ix1];
                        float cn1 = sigA(v3) * c1ld + sigA(v2) * tanhA(u3);
                        float hn1 = sigA(u2) * tanhA(cn1);
                        g_c[ix1] = cn1; oseq[ix1] = hn1;
                    }
                }
            }
            __syncthreads();   // protect smem before next job's staging
        }
    } else {
        // ================= f32x2 role =================
        // smem: ws float[16][256] at 0 (16KB); xs2 u64[64][17] at 16384
        float (*ws)[256] = (float(*)[256])sm;
        unsigned long long (*xs2)[17] = (unsigned long long(*)[17])(sm + 16384);
        const int fid = bid - NSM;
        const int rg = fid >> 1;
        const int y2 = fid & 1;
        const int row0 = n1 + rg * 64;
        const int tx = lane;
        const int ty = wid;

        unsigned long long acc[8][4];
#pragma unroll
        for (int i = 0; i < 8; i++)
#pragma unroll
            for (int q = 0; q < 4; q++) acc[i][q] = 0ull;

        for (int k0 = 0; k0 < 128; k0 += 16) {
            // stage W: 16 x 256 floats
#pragma unroll
            for (int it = 0; it < 4; it++) {
                int idx = tid + it * 256;         // 0..1023
                int r = idx >> 6, c4 = idx & 63;
                float4 v = __ldg((const float4*)(g_Wp + (size_t)(k0 + r) * 512 + y2 * 256 + c4 * 4));
                *(float4*)&ws[r][c4 * 4] = v;
            }
            // stage X: reconstruct z = zh + zl
            {
                int r = tid >> 2, kk = (tid & 3) * 4;
                int row = row0 + r;
                if (row < n) {
                    uint2 hv = *(const uint2*)(g_zh + (size_t)row * 128 + k0 + kk);
                    uint2 lv = *(const uint2*)(g_zl + (size_t)row * 128 + k0 + kk);
                    const __nv_bfloat16* hp = (const __nv_bfloat16*)&hv;
                    const __nv_bfloat16* lp = (const __nv_bfloat16*)&lv;
#pragma unroll
                    for (int m = 0; m < 4; m++)
                        xs2[r][kk + m] = pk2(__bfloat162float(hp[m]) + __bfloat162float(lp[m]));
                } else {
#pragma unroll
                    for (int m = 0; m < 4; m++) xs2[r][kk + m] = 0ull;
                }
            }
            __syncthreads();
#pragma unroll
            for (int k = 0; k < 16; k++) {
                unsigned long long w2[4];
                const unsigned long long* wp0 = (const unsigned long long*)&ws[k][tx * 4];
                const unsigned long long* wp1 = (const unsigned long long*)&ws[k][128 + tx * 4];
                w2[0] = wp0[0]; w2[1] = wp0[1];
                w2[2] = wp1[0]; w2[3] = wp1[1];
#pragma unroll
                for (int i = 0; i < 8; i++) {
                    unsigned long long xx = xs2[ty + 8 * i][k];
#pragma unroll
                    for (int q = 0; q < 4; q++) FMA2(acc[i][q], xx, w2[q]);
                }
            }
            __syncthreads();
        }

        // epilogue: thread cols P = y2*256 + h*128 + 4*tx, gates in float4
#pragma unroll
        for (int i = 0; i < 8; i++) {
            int r = row0 + ty + 8 * i;
            if (r >= n) continue;
            float v[8];
            upk2(v[0], v[1], acc[i][0]); upk2(v[2], v[3], acc[i][1]);
            upk2(v[4], v[5], acc[i][2]); upk2(v[6], v[7], acc[i][3]);
#pragma unroll
            for (int hh = 0; hh < 2; hh++) {
                int P = y2 * 256 + hh * 128 + 4 * tx;
                float4 bb = *(const float4*)(baseb + (size_t)r * 512 + P);
                float iv = v[4 * hh + 0] + bb.x;
                float fv = v[4 * hh + 1] + bb.y;
                float ov = v[4 * hh + 2] + bb.z;
                float gv = v[4 * hh + 3] + bb.w;
                int hcol = P >> 2;
                size_t ix = (size_t)r * 128 + hcol;
                float cold = g_c[ix];
                float cn = sigA(fv) * cold + sigA(iv) * tanhA(gv);
                float hn = sigA(ov) * tanhA(cn);
                g_c[ix] = cn;
                oseq[ix] = hn;
            }
        }
    }
}

// ---------------- bf16 split-3 tensor GEMM (init + base precompute) ----------------
// mode 0: o512[r*512 + P] = D + bc[orig col]   (permuted base precompute)
// mode 2: init: elu(D + bi[col]) -> g_h (cols<128) / g_c
__global__ void __launch_bounds__(256, 2)
k_mma(const __nv_bfloat16* __restrict__ Ah, const __nv_bfloat16* __restrict__ Al, int lda,
      const __nv_bfloat16* __restrict__ Bh, const __nv_bfloat16* __restrict__ Bl,
      int K, const float* __restrict__ aux, float* __restrict__ o512, int n, int mode) {
    extern __shared__ char sm[];
    const uint32_t sb = smem_u32(sm);
    const int tid = threadIdx.x;
    const int lane = tid & 31;
    const int wid = tid >> 5;
    const int m0 = blockIdx.x * 128;
    const int t = blockIdx.y;
    const int mw = (wid & 3) * 32;
    const int nw = (wid >> 2) * 64;

    float acc[2][8][4];
#pragma unroll
    for (int i = 0; i < 2; i++)
#pragma unroll
        for (int j = 0; j < 8; j++)
#pragma unroll
            for (int q = 0; q < 4; q++) acc[i][j][q] = 0.f;

    const int nslab = K >> 5;

    auto stage = [&](int ks) {
        uint32_t bufo = (uint32_t)(ks % 3) * 32768;
#pragma unroll
        for (int it = 0; it < 8; it++) {
            int id = tid + it * 256;
            int arr = id >> 9;
            int rem = id & 511;
            int row = rem >> 2, g = rem & 3;
            uint32_t dst = sb + bufo + arr * 8192 + swz(row, g);
            if (arr < 2) {
                const __nv_bfloat16* src = (arr == 0 ? Ah : Al)
                    + (size_t)(m0 + row) * lda + ks * 32 + g * 8;
                int ok = (m0 + row < n) ? 16 : 0;
                CP16(dst, src, ok);
            } else {
                const __nv_bfloat16* src = (arr == 2 ? Bh : Bl)
                    + (size_t)(t * 128 + row) * K + ks * 32 + g * 8;
                CP16(dst, src, 16);
            }
        }
        CP_COMMIT();
    };

    stage(0);
    stage(1);
    for (int ks = 0; ks < nslab; ks++) {
        if (ks == nslab - 1) { CP_WAIT(0); } else { CP_WAIT(1); }
        __syncthreads();
        if (ks + 2 < nslab) stage(ks + 2);
        uint32_t abase = sb + (uint32_t)(ks % 3) * 32768;
        uint32_t bbase = abase + 16384;
#pragma unroll
        for (int kc = 0; kc < 2; kc++) {
            uint32_t ah[2][4], al[2][4];
#pragma unroll
            for (int mf = 0; mf < 2; mf++) {
                int row = mw + mf * 16 + (lane & 15);
                int g = kc * 2 + (lane >> 4);
                uint32_t a = abase + swz(row, g);
                LDSM4(ah[mf][0], ah[mf][1], ah[mf][2], ah[mf][3], a);
                LDSM4(al[mf][0], al[mf][1], al[mf][2], al[mf][3], a + 8192);
            }
#pragma unroll
            for (int bp = 0; bp < 4; bp++) {
                int p = nw + bp * 16 + ((lane >> 4) << 3) + (lane & 7);
                int g = kc * 2 + ((lane >> 3) & 1);
                uint32_t a = bbase + swz(p, g);
                uint32_t h0, h1, h2, h3, l0, l1, l2, l3;
                LDSM4(h0, h1, h2, h3, a);
                LDSM4(l0, l1, l2, l3, a + 8192);
                MMA16816(acc[0][2 * bp],     ah[0][0], ah[0][1], ah[0][2], ah[0][3], h0, h1);
                MMA16816(acc[1][2 * bp],     ah[1][0], ah[1][1], ah[1][2], ah[1][3], h0, h1);
                MMA16816(acc[0][2 * bp + 1], ah[0][0], ah[0][1], ah[0][2], ah[0][3], h2, h3);
                MMA16816(acc[1][2 * bp + 1], ah[1][0], ah[1][1], ah[1][2], ah[1][3], h2, h3);
                MMA16816(acc[0][2 * bp],     ah[0][0], ah[0][1], ah[0][2], ah[0][3], l0, l1);
                MMA16816(acc[1][2 * bp],     ah[1][0], ah[1][1], ah[1][2], ah[1][3], l0, l1);
                MMA16816(acc[0][2 * bp + 1], ah[0][0], ah[0][1], ah[0][2], ah[0][3], l2, l3);
                MMA16816(acc[1][2 * bp + 1], ah[1][0], ah[1][1], ah[1][2], ah[1][3], l2, l3);
                MMA16816(acc[0][2 * bp],     al[0][0], al[0][1], al[0][2], al[0][3], h0, h1);
                MMA16816(acc[1][2 * bp],     al[1][0], al[1][1], al[1][2], al[1][3], h0, h1);
                MMA16816(acc[0][2 * bp + 1], al[0][0], al[0][1], al[0][2], al[0][3], h2, h3);
                MMA16816(acc[1][2 * bp + 1], al[1][0], al[1][1], al[1][2], al[1][3], h2, h3);
            }
        }
    }

#pragma unroll
    for (int mf = 0; mf < 2; mf++) {
        int r0 = m0 + mw + mf * 16 + (lane >> 2);
        int r1 = r0 + 8;
#pragma unroll
        for (int nf = 0; nf < 8; nf++) {
            float d0 = acc[mf][nf][0], d1 = acc[mf][nf][1];
            float d2 = acc[mf][nf][2], d3 = acc[mf][nf][3];
            int c0 = nw + nf * 8 + (lane & 3) * 2;
            if (mode == 2) {
                int gc = t * 128 + c0;
                float2 bb = *(const float2*)(aux + gc);
                float* dst = (gc < 128) ? (g_h + gc) : (g_c + gc - 128);
                if (r0 < n) {
                    float e0 = d0 + bb.x, e1 = d1 + bb.y;
                    e0 = (e0 > 0.f) ? e0 : expm1f(e0);
                    e1 = (e1 > 0.f) ? e1 : expm1f(e1);
                    float2 o; o.x = e0; o.y = e1;
                    *(float2*)(dst + (size_t)r0 * 128) = o;
                }
                if (r1 < n) {
                    float e0 = d2 + bb.x, e1 = d3 + bb.y;
                    e0 = (e0 > 0.f) ? e0 : expm1f(e0);
                    e1 = (e1 > 0.f) ? e1 : expm1f(e1);
                    float2 o; o.x = e0; o.y = e1;
                    *(float2*)(dst + (size_t)r1 * 128) = o;
                }
            } else {
                int P = t * 128 + c0;
                float bb0 = aux[(P & 3) * 128 + (P >> 2)];
                float bb1 = aux[((P + 1) & 3) * 128 + ((P + 1) >> 2)];
                if (r0 < n) {
                    float2 o; o.x = d0 + bb0; o.y = d1 + bb1;
                    *(float2*)(o512 + (size_t)r0 * 512 + P) = o;
                }
                if (r1 < n) {
                    float2 o; o.x = d2 + bb0; o.y = d3 + bb1;
                    *(float2*)(o512 + (size_t)r1 * 512 + P) = o;
                }
            }
        }
    }
}

// ---------------- host launcher ----------------
extern "C" void kernel_launch(void* const* d_in, const int* in_sizes, int n_in,
                              void* d_out, int out_size) {
    const float* h  = (const float*)d_in[0];
    const float* c  = (const float*)d_in[1];
    const void*  ei = d_in[2];
    const float* ea = (const float*)d_in[3];
    const float* Wi = (const float*)d_in[4];
    const float* bi = (const float*)d_in[5];
    const float* Wc = (const float*)d_in[6];
    const float* bc = (const float*)d_in[7];
    float* out = (float*)d_out;

    int n   = in_sizes[0] / 128;
    int E   = in_sizes[3];
    int seq = out_size / (n * 128);

    static float* p_base = nullptr;
    static float* p_h = nullptr;
    static __nv_bfloat16 *p_Ph, *p_Pl, *p_zh, *p_zl, *p_WTh, *p_WTl, *p_WIh, *p_WIl;
    static int NSM = 148;
    if (!p_base) {
        cudaGetSymbolAddress((void**)&p_base, g_base);
        cudaGetSymbolAddress((void**)&p_h, g_h);
        cudaGetSymbolAddress((void**)&p_Ph, g_Ph);
        cudaGetSymbolAddress((void**)&p_Pl, g_Pl);
        cudaGetSymbolAddress((void**)&p_zh, g_zh);
        cudaGetSymbolAddress((void**)&p_zl, g_zl);
        cudaGetSymbolAddress((void**)&p_WTh, g_WTh);
        cudaGetSymbolAddress((void**)&p_WTl, g_WTl);
        cudaGetSymbolAddress((void**)&p_WIh, g_WIh);
        cudaGetSymbolAddress((void**)&p_WIl, g_WIl);
        cudaFuncSetAttribute(k_mma, cudaFuncAttributeMaxDynamicSharedMemorySize, 98304);
        cudaFuncSetAttribute(k_seq, cudaFuncAttributeMaxDynamicSharedMemorySize, 98304);
        int smc = 0;
        if (cudaDeviceGetAttribute(&smc, cudaDevAttrMultiProcessorCount, 0) == cudaSuccess && smc > 0)
            NSM = smc;
    }

    int nb256 = (n + 255) / 256;
    int eb256 = (E + 255) / 256;
    int nb1024 = (n + 1023) / 1024;
    int mtiles = (n + 127) / 128;
    int prop_blocks = (n * 32 + 255) / 256;
    size_t smem_sz = 98304;

    // row split for heterogeneous sequence kernel
    int mt1 = (11 * mtiles) / 20;                 // ~55% of tiles to HMMA role
    if (mt1 < 1) mt1 = (mtiles >= 1) ? 1 : 0;
    int n1 = mt1 * 128;
    if (n1 > n) { n1 = n & ~127; mt1 = n1 / 128; }
    int frows = n - n1;
    int nf2 = (frows > 0) ? (((frows + 63) / 64) * 2) : 0;
    int seq_grid = NSM + nf2;

    // ---- graph setup (per launch; deterministic) ----
    k_init<<<nb256, 256>>>(n);
    k_detect<<<1, 128>>>((const unsigned int*)ei);
    k_build<<<eb256, 256>>>(ei, ea, E);
    k_scan1<<<nb1024, 1024>>>(n);        // also computes dinv
    k_scan2<<<1, 32>>>(nb1024);
    k_scan3<<<nb1024, 1024>>>(n);
    k_scatter<<<eb256, 256>>>(ea, E);
    k_split<<<1024, 256>>>(Wc, Wi);

    // ---- loop-invariant precompute ----
    k_prop<<<dim3(prop_blocks, 2), 256>>>(h, c, p_Ph, p_Pl, 256, n);
    // init: elu(Phc @ W_init + b_init) -> g_h, g_c
    k_mma<<<dim3(mtiles, 2), 256, smem_sz>>>(p_Ph, p_Pl, 256, p_WIh, p_WIl, 256,
                                             bi, nullptr, n, 2);
    // base_perm = P_h @ Wc[0:128] + b_cell
    k_mma<<<dim3(mtiles, 4), 256, smem_sz>>>(p_Ph, p_Pl, 256, p_WTh, p_WTl, 128,
                                             bc, p_base, n, 0);

    // ---- sequence: h(t) lives in out[t-1] slab ----
    const float* hsrc = p_h;
    for (int tt = 0; tt < seq; tt++) {
        k_prop<<<dim3(prop_blocks, 1), 256>>>(hsrc, nullptr, p_zh, p_zl, 128, n);
        float* odst = out + (long long)tt * n * 128;
        k_seq<<<seq_grid, 256, smem_sz>>>(p_base, odst, n, n1, mt1, NSM);
        hsrc = odst;
    }
}

// round 12
// speedup vs baseline: 1.1897x; 1.1897x over previous
#include <cuda_runtime.h>
#include <cuda_bf16.h>
#include <math.h>
#include <stdint.h>

#define MAXN 20000
#define MAXE 320000

// ---------------- device scratch (no allocs allowed) ----------------
__device__ int   g_is64;
__device__ int   g_src[MAXE];
__device__ int   g_dst[MAXE];
__device__ int   g_esrc[MAXE];
__device__ float g_ewn[MAXE];
__device__ float g_deg[MAXN];
__device__ float g_dinv[MAXN];
__device__ int   g_cnt[MAXN];
__device__ int   g_rowptr[MAXN + 1];
__device__ int   g_cursor[MAXN];
__device__ int   g_part[32];
__device__ int   g_off2[32];
__device__ int   g_total;
__device__ float g_base[(long long)MAXN * 512];   // permuted gate layout [r][P], P = hcol*4 + gate
__device__ float g_h[MAXN * 128];
__device__ float g_c[MAXN * 128];
// bf16-split activations
__device__ __nv_bfloat16 g_Ph[MAXN * 256];   // [P_h | P_c] hi
__device__ __nv_bfloat16 g_Pl[MAXN * 256];   // lo
__device__ __nv_bfloat16 g_zh[MAXN * 128];
__device__ __nv_bfloat16 g_zl[MAXN * 128];
// bf16-split transposed weights, perm P = hcol*4 + gate
__device__ __nv_bfloat16 g_WTh[2 * 512 * 128];
__device__ __nv_bfloat16 g_WTl[2 * 512 * 128];
__device__ __nv_bfloat16 g_WIh[256 * 256];
__device__ __nv_bfloat16 g_WIl[256 * 256];

// ---------------- helpers ----------------
__device__ __forceinline__ float tanhA(float x) {
    float r; asm("tanh.approx.f32 %0, %1;" : "=f"(r) : "f"(x)); return r;
}
__device__ __forceinline__ float sigA(float x) {
    return fmaf(tanhA(0.5f * x), 0.5f, 0.5f);
}
__device__ __forceinline__ uint32_t smem_u32(const void* p) {
    uint32_t a;
    asm("{ .reg .u64 t; cvta.to.shared.u64 t, %1; cvt.u32.u64 %0, t; }" : "=r"(a) : "l"(p));
    return a;
}

#define CP16(dst, src, srcsz) \
    asm volatile("cp.async.ca.shared.global [%0], [%1], 16, %2;" \
        :: "r"(dst), "l"(src), "r"(srcsz))
#define CP_COMMIT() asm volatile("cp.async.commit_group;" ::: "memory")
#define CP_WAIT(nn) asm volatile("cp.async.wait_group %0;" :: "n"(nn) : "memory")

#define LDSM4(r0, r1, r2, r3, a) \
    asm volatile("ldmatrix.sync.aligned.m8n8.x4.shared.b16 {%0,%1,%2,%3}, [%4];" \
        : "=r"(r0), "=r"(r1), "=r"(r2), "=r"(r3) : "r"(a))

#define MMA16816(d, a0, a1, a2, a3, b0, b1) \
    asm volatile("mma.sync.aligned.m16n8k16.row.col.f32.bf16.bf16.f32 " \
        "{%0,%1,%2,%3}, {%4,%5,%6,%7}, {%8,%9}, {%0,%1,%2,%3};" \
        : "+f"((d)[0]), "+f"((d)[1]), "+f"((d)[2]), "+f"((d)[3]) \
        : "r"(a0), "r"(a1), "r"(a2), "r"(a3), "r"(b0), "r"(b1))

// smem swizzle: 64B rows, 4x16B granules, conflict-free for 8-row LDSM phases
__device__ __forceinline__ uint32_t swz(int row, int g) {
    return (uint32_t)(row * 64 + ((g ^ ((row >> 1) & 3)) << 4));
}

// ---------------- setup kernels ----------------
__global__ void k_init(int n) {
    int i = blockIdx.x * blockDim.x + threadIdx.x;
    if (i < n) { g_deg[i] = 0.f; g_cnt[i] = 0; }
    if (i == 0) g_is64 = 1;
}

__global__ void k_detect(const unsigned int* __restrict__ w) {
    unsigned int v = w[2 * threadIdx.x + 1];
    if (v != 0u) g_is64 = 0;
}

__global__ void k_build(const void* __restrict__ ei, const float* __restrict__ ea, int E) {
    int e = blockIdx.x * blockDim.x + threadIdx.x;
    if (e >= E) return;
    int s, d;
    if (g_is64) {
        const long long* p = (const long long*)ei;
        s = (int)p[e]; d = (int)p[E + e];
    } else {
        const int* p = (const int*)ei;
        s = p[e]; d = p[E + e];
    }
    g_src[e] = s; g_dst[e] = d;
    atomicAdd(&g_deg[d], ea[e]);
    atomicAdd(&g_cnt[d], 1);
}

// hierarchical scan pass 1 (+ dinv fused)
__global__ void k_scan1(int n) {
    __shared__ int s[1024];
    int i = blockIdx.x * 1024 + threadIdx.x;
    if (i < n) g_dinv[i] = rsqrtf(g_deg[i] + 1.0f);
    int v = (i < n) ? g_cnt[i] : 0;
    s[threadIdx.x] = v;
    __syncthreads();
    for (int off = 1; off < 1024; off <<= 1) {
        int t = (threadIdx.x >= off) ? s[threadIdx.x - off] : 0;
        __syncthreads();
        s[threadIdx.x] += t;
        __syncthreads();
    }
    if (i < n) g_rowptr[i] = s[threadIdx.x] - v;   // local exclusive
    if (threadIdx.x == 1023) g_part[blockIdx.x] = s[1023];
}

__global__ void k_scan2(int nb) {
    int tid = threadIdx.x;                 // 32 threads
    int v = (tid < nb) ? g_part[tid] : 0;
    int incl = v;
    for (int o = 1; o < 32; o <<= 1) {
        int t = __shfl_up_sync(0xffffffffu, incl, o);
        if (tid >= o) incl += t;
    }
    if (tid < nb) g_off2[tid] = incl - v;
    if (tid == 31) g_total = incl;
}

__global__ void k_scan3(int n) {
    int i = blockIdx.x * 1024 + threadIdx.x;
    if (i < n) {
        int val = g_rowptr[i] + g_off2[blockIdx.x];
        g_rowptr[i] = val;
        g_cursor[i] = val;
    }
    if (i == 0) g_rowptr[n] = g_total;
}

__global__ void k_scatter(const float* __restrict__ ea, int E) {
    int e = blockIdx.x * blockDim.x + threadIdx.x;
    if (e >= E) return;
    int s = g_src[e], d = g_dst[e];
    int pos = atomicAdd(&g_cursor[d], 1);
    g_esrc[pos] = s;
    g_ewn[pos] = g_dinv[s] * ea[e] * g_dinv[d];
}

// fused weight transpose + permute + bf16 split (W_cell and W_init)
// ids [0, 131072): W_cell  perm P = hcol*4 + q  <->  orig col q*128 + hcol
// ids [131072, 196608): W_init transposed [p][k] = Wi[k][p]
__global__ void k_split(const float* __restrict__ Wc, const float* __restrict__ Wi) {
    int id = blockIdx.x * blockDim.x + threadIdx.x;   // 0 .. 196607
    if (id < 131072) {
        int m = id >> 16;
        int rem = id & 65535;
        int p = rem >> 7;
        int k = rem & 127;
        int hcol = p >> 2, q = p & 3;
        int nc = q * 128 + hcol;
        float v = Wc[(long long)(m * 128 + k) * 512 + nc];
        __nv_bfloat16 hb = __float2bfloat16_rn(v);
        float lf = v - __bfloat162float(hb);
        g_WTh[id] = hb;
        g_WTl[id] = __float2bfloat16_rn(lf);
    } else {
        int id2 = id - 131072;
        int p = id2 >> 8;
        int k = id2 & 255;
        float v = Wi[(long long)k * 256 + p];
        __nv_bfloat16 hb = __float2bfloat16_rn(v);
        float lf = v - __bfloat162float(hb);
        g_WIh[id2] = hb;
        g_WIl[id2] = __float2bfloat16_rn(lf);
    }
}

// ---------------- sparse propagate -> bf16 hi/lo split output ----------------
__global__ void k_prop(const float* __restrict__ x0, const float* __restrict__ x1,
                       __nv_bfloat16* __restrict__ oh, __nv_bfloat16* __restrict__ ol,
                       int ldo, int n) {
    const float* x = blockIdx.y ? x1 : x0;
    int coff = blockIdx.y * 128;
    int v = (blockIdx.x * blockDim.x + threadIdx.x) >> 5;
    int lane = threadIdx.x & 31;
    if (v >= n) return;
    int beg = g_rowptr[v], end = g_rowptr[v + 1];
    float ax = 0.f, ay = 0.f, az = 0.f, aw = 0.f;
    int e = beg;
    for (; e + 1 < end; e += 2) {
        int s0 = g_esrc[e], s1 = g_esrc[e + 1];
        float w0 = g_ewn[e], w1 = g_ewn[e + 1];
        float4 v0 = __ldg((const float4*)(x + (long long)s0 * 128) + lane);
        float4 v1 = __ldg((const float4*)(x + (long long)s1 * 128) + lane);
        ax = fmaf(w0, v0.x, ax); ay = fmaf(w0, v0.y, ay);
        az = fmaf(w0, v0.z, az); aw = fmaf(w0, v0.w, aw);
        ax = fmaf(w1, v1.x, ax); ay = fmaf(w1, v1.y, ay);
        az = fmaf(w1, v1.z, az); aw = fmaf(w1, v1.w, aw);
    }
    if (e < end) {
        int s0 = g_esrc[e];
        float w0 = g_ewn[e];
        float4 v0 = __ldg((const float4*)(x + (long long)s0 * 128) + lane);
        ax = fmaf(w0, v0.x, ax); ay = fmaf(w0, v0.y, ay);
        az = fmaf(w0, v0.z, az); aw = fmaf(w0, v0.w, aw);
    }
    float di = g_dinv[v];
    float w2 = di * di;
    float4 vv = __ldg((const float4*)(x + (long long)v * 128) + lane);
    ax = fmaf(w2, vv.x, ax); ay = fmaf(w2, vv.y, ay);
    az = fmaf(w2, vv.z, az); aw = fmaf(w2, vv.w, aw);
    float a[4] = {ax, ay, az, aw};
    unsigned short hs[4], ls[4];
#pragma unroll
    for (int m = 0; m < 4; m++) {
        __nv_bfloat16 hb = __float2bfloat16_rn(a[m]);
        float lf = a[m] - __bfloat162float(hb);
        __nv_bfloat16 lb = __float2bfloat16_rn(lf);
        hs[m] = *(unsigned short*)&hb;
        ls[m] = *(unsigned short*)&lb;
    }
    *(uint2*)(oh + (long long)v * ldo + coff + lane * 4) = *(uint2*)hs;
    *(uint2*)(ol + (long long)v * ldo + coff + lane * 4) = *(uint2*)ls;
}

// ---------------- sequence GEMM: M64 x N128 tile, 3 CTAs/SM target ----------------
// C[64 x 128] = z[m0:m0+64, :128] @ W1[t*128:(t+1)*128, :128]^T  (bf16 split-3)
// smem per 24KB stage: Ah[0,4K) Al[4K,8K) Bh[8K,16K) Bl[16K,24K); 64B swizzled rows.
// gates = D + base_perm; LSTM update g_c; write oseq.
__global__ void __launch_bounds__(256, 3)
k_mmaS(const float* __restrict__ baseb, float* __restrict__ oseq, int n) {
    extern __shared__ char sm[];
    const uint32_t sb = smem_u32(sm);
    const int tid = threadIdx.x;
    const int lane = tid & 31;
    const int wid = tid >> 5;
    const int m0 = blockIdx.x * 64;
    const int t = blockIdx.y;
    const int mw = (wid & 1) * 32;
    const int nw = (wid >> 1) * 32;
    const __nv_bfloat16* Ah = g_zh;
    const __nv_bfloat16* Al = g_zl;
    const __nv_bfloat16* Bh = g_WTh + 512 * 128;
    const __nv_bfloat16* Bl = g_WTl + 512 * 128;

    float acc[2][4][4];
#pragma unroll
    for (int i = 0; i < 2; i++)
#pragma unroll
        for (int j = 0; j < 4; j++)
#pragma unroll
            for (int q = 0; q < 4; q++) acc[i][j][q] = 0.f;

    auto stage = [&](int ks) {
        uint32_t bufo = (uint32_t)(ks & 1) * 24576;
#pragma unroll
        for (int it = 0; it < 6; it++) {
            int id = tid + it * 256;        // 0..1535
            if (id < 512) {
                int arr = id >> 8;          // 0:Ah 1:Al
                int rem = id & 255;
                int row = rem >> 2, g = rem & 3;
                uint32_t dst = sb + bufo + arr * 4096 + swz(row, g);
                const __nv_bfloat16* src = (arr == 0 ? Ah : Al)
                    + (size_t)(m0 + row) * 128 + ks * 32 + g * 8;
                int ok = (m0 + row < n) ? 16 : 0;
                CP16(dst, src, ok);
            } else {
                int id2 = id - 512;         // 0..1023
                int arr = id2 >> 9;         // 0:Bh 1:Bl
                int rem = id2 & 511;
                int row = rem >> 2, g = rem & 3;
                uint32_t dst = sb + bufo + 8192 + arr * 8192 + swz(row, g);
                const __nv_bfloat16* src = (arr == 0 ? Bh : Bl)
                    + (size_t)(t * 128 + row) * 128 + ks * 32 + g * 8;
                CP16(dst, src, 16);
            }
        }
        CP_COMMIT();
    };

    stage(0);
#pragma unroll
    for (int ks = 0; ks < 4; ks++) {
        if (ks + 1 < 4) { stage(ks + 1); CP_WAIT(1); } else { CP_WAIT(0); }
        __syncthreads();
        uint32_t abase = sb + (uint32_t)(ks & 1) * 24576;
        uint32_t bbase = abase + 8192;
#pragma unroll
        for (int kc = 0; kc < 2; kc++) {
            uint32_t ah[2][4], al[2][4];
#pragma unroll
            for (int mf = 0; mf < 2; mf++) {
                int row = mw + mf * 16 + (lane & 15);
                int g = kc * 2 + (lane >> 4);
                uint32_t a = abase + swz(row, g);
                LDSM4(ah[mf][0], ah[mf][1], ah[mf][2], ah[mf][3], a);
                LDSM4(al[mf][0], al[mf][1], al[mf][2], al[mf][3], a + 4096);
            }
            uint32_t bh[2][4], bl[2][4];
#pragma unroll
            for (int bp = 0; bp < 2; bp++) {
                int p = nw + bp * 16 + ((lane >> 4) << 3) + (lane & 7);
                int g = kc * 2 + ((lane >> 3) & 1);
                uint32_t a = bbase + swz(p, g);
                LDSM4(bh[bp][0], bh[bp][1], bh[bp][2], bh[bp][3], a);
                LDSM4(bl[bp][0], bl[bp][1], bl[bp][2], bl[bp][3], a + 8192);
            }
            // 24 MMAs, term-major (reuse distance 8)
#pragma unroll
            for (int bp = 0; bp < 2; bp++) {
                MMA16816(acc[0][2 * bp],     ah[0][0], ah[0][1], ah[0][2], ah[0][3], bh[bp][0], bh[bp][1]);
                MMA16816(acc[1][2 * bp],     ah[1][0], ah[1][1], ah[1][2], ah[1][3], bh[bp][0], bh[bp][1]);
                MMA16816(acc[0][2 * bp + 1], ah[0][0], ah[0][1], ah[0][2], ah[0][3], bh[bp][2], bh[bp][3]);
                MMA16816(acc[1][2 * bp + 1], ah[1][0], ah[1][1], ah[1][2], ah[1][3], bh[bp][2], bh[bp][3]);
            }
#pragma unroll
            for (int bp = 0; bp < 2; bp++) {
                MMA16816(acc[0][2 * bp],     ah[0][0], ah[0][1], ah[0][2], ah[0][3], bl[bp][0], bl[bp][1]);
                MMA16816(acc[1][2 * bp],     ah[1][0], ah[1][1], ah[1][2], ah[1][3], bl[bp][0], bl[bp][1]);
                MMA16816(acc[0][2 * bp + 1], ah[0][0], ah[0][1], ah[0][2], ah[0][3], bl[bp][2], bl[bp][3]);
                MMA16816(acc[1][2 * bp + 1], ah[1][0], ah[1][1], ah[1][2], ah[1][3], bl[bp][2], bl[bp][3]);
            }
#pragma unroll
            for (int bp = 0; bp < 2; bp++) {
                MMA16816(acc[0][2 * bp],     al[0][0], al[0][1], al[0][2], al[0][3], bh[bp][0], bh[bp][1]);
                MMA16816(acc[1][2 * bp],     al[1][0], al[1][1], al[1][2], al[1][3], bh[bp][0], bh[bp][1]);
                MMA16816(acc[0][2 * bp + 1], al[0][0], al[0][1], al[0][2], al[0][3], bh[bp][2], bh[bp][3]);
                MMA16816(acc[1][2 * bp + 1], al[1][0], al[1][1], al[1][2], al[1][3], bh[bp][2], bh[bp][3]);
            }
        }
        __syncthreads();
    }

    // ---- LSTM epilogue ----
#pragma unroll
    for (int mf = 0; mf < 2; mf++) {
        int r0 = m0 + mw + mf * 16 + (lane >> 2);
        int r1 = r0 + 8;
#pragma unroll
        for (int nf = 0; nf < 4; nf++) {
            float d0 = acc[mf][nf][0], d1 = acc[mf][nf][1];
            float d2 = acc[mf][nf][2], d3 = acc[mf][nf][3];
            int c0 = nw + nf * 8 + (lane & 3) * 2;
            int P0 = t * 128 + c0;
            float2 b0 = make_float2(0.f, 0.f), b1 = make_float2(0.f, 0.f);
            if (r0 < n) b0 = *(const float2*)(baseb + (size_t)r0 * 512 + P0);
            if (r1 < n) b1 = *(const float2*)(baseb + (size_t)r1 * 512 + P0);
            float v0 = d0 + b0.x, v1 = d1 + b0.y;
            float v2 = d2 + b1.x, v3 = d3 + b1.y;
            float u0 = __shfl_xor_sync(0xffffffffu, v0, 1);
            float u1 = __shfl_xor_sync(0xffffffffu, v1, 1);
            float u2 = __shfl_xor_sync(0xffffffffu, v2, 1);
            float u3 = __shfl_xor_sync(0xffffffffu, v3, 1);
            if (!(lane & 1)) {
                // this lane: (i, f); partner: (o, g)
                int hcol = P0 >> 2;
                if (r0 < n) {
                    size_t ix = (size_t)r0 * 128 + hcol;
                    float cold = g_c[ix];
                    float cn = sigA(v1) * cold + sigA(v0) * tanhA(u1);
                    float hn = sigA(u0) * tanhA(cn);
                    g_c[ix] = cn; oseq[ix] = hn;
                }
                if (r1 < n) {
                    size_t ix = (size_t)r1 * 128 + hcol;
                    float cold = g_c[ix];
                    float cn = sigA(v3) * cold + sigA(v2) * tanhA(u3);
                    float hn = sigA(u2) * tanhA(cn);
                    g_c[ix] = cn; oseq[ix] = hn;
                }
            }
        }
    }
}

// ---------------- bf16 split-3 tensor GEMM (init + base precompute) ----------------
// mode 0: o512[r*512 + P] = D + bc[orig col]   (permuted base precompute)
// mode 2: init: elu(D + bi[col]) -> g_h (cols<128) / g_c
__global__ void __launch_bounds__(256, 2)
k_mma(const __nv_bfloat16* __restrict__ Ah, const __nv_bfloat16* __restrict__ Al, int lda,
      const __nv_bfloat16* __restrict__ Bh, const __nv_bfloat16* __restrict__ Bl,
      int K, const float* __restrict__ aux, float* __restrict__ o512, int n, int mode) {
    extern __shared__ char sm[];
    const uint32_t sb = smem_u32(sm);
    const int tid = threadIdx.x;
    const int lane = tid & 31;
    const int wid = tid >> 5;
    const int m0 = blockIdx.x * 128;
    const int t = blockIdx.y;
    const int mw = (wid & 3) * 32;
    const int nw = (wid >> 2) * 64;

    float acc[2][8][4];
#pragma unroll
    for (int i = 0; i < 2; i++)
#pragma unroll
        for (int j = 0; j < 8; j++)
#pragma unroll
            for (int q = 0; q < 4; q++) acc[i][j][q] = 0.f;

    const int nslab = K >> 5;

    auto stage = [&](int ks) {
        uint32_t bufo = (uint32_t)(ks % 3) * 32768;
#pragma unroll
        for (int it = 0; it < 8; it++) {
            int id = tid + it * 256;
            int arr = id >> 9;
            int rem = id & 511;
            int row = rem >> 2, g = rem & 3;
            uint32_t dst = sb + bufo + arr * 8192 + swz(row, g);
            if (arr < 2) {
                const __nv_bfloat16* src = (arr == 0 ? Ah : Al)
                    + (size_t)(m0 + row) * lda + ks * 32 + g * 8;
                int ok = (m0 + row < n) ? 16 : 0;
                CP16(dst, src, ok);
            } else {
                const __nv_bfloat16* src = (arr == 2 ? Bh : Bl)
                    + (size_t)(t * 128 + row) * K + ks * 32 + g * 8;
                CP16(dst, src, 16);
            }
        }
        CP_COMMIT();
    };

    stage(0);
    stage(1);
    for (int ks = 0; ks < nslab; ks++) {
        if (ks == nslab - 1) { CP_WAIT(0); } else { CP_WAIT(1); }
        __syncthreads();
        if (ks + 2 < nslab) stage(ks + 2);
        uint32_t abase = sb + (uint32_t)(ks % 3) * 32768;
        uint32_t bbase = abase + 16384;
#pragma unroll
        for (int kc = 0; kc < 2; kc++) {
            uint32_t ah[2][4], al[2][4];
#pragma unroll
            for (int mf = 0; mf < 2; mf++) {
                int row = mw + mf * 16 + (lane & 15);
                int g = kc * 2 + (lane >> 4);
                uint32_t a = abase + swz(row, g);
                LDSM4(ah[mf][0], ah[mf][1], ah[mf][2], ah[mf][3], a);
                LDSM4(al[mf][0], al[mf][1], al[mf][2], al[mf][3], a + 8192);
            }
#pragma unroll
            for (int bp = 0; bp < 4; bp++) {
                int p = nw + bp * 16 + ((lane >> 4) << 3) + (lane & 7);
                int g = kc * 2 + ((lane >> 3) & 1);
                uint32_t a = bbase + swz(p, g);
                uint32_t h0, h1, h2, h3, l0, l1, l2, l3;
                LDSM4(h0, h1, h2, h3, a);
                LDSM4(l0, l1, l2, l3, a + 8192);
                MMA16816(acc[0][2 * bp],     ah[0][0], ah[0][1], ah[0][2], ah[0][3], h0, h1);
                MMA16816(acc[1][2 * bp],     ah[1][0], ah[1][1], ah[1][2], ah[1][3], h0, h1);
                MMA16816(acc[0][2 * bp + 1], ah[0][0], ah[0][1], ah[0][2], ah[0][3], h2, h3);
                MMA16816(acc[1][2 * bp + 1], ah[1][0], ah[1][1], ah[1][2], ah[1][3], h2, h3);
                MMA16816(acc[0][2 * bp],     ah[0][0], ah[0][1], ah[0][2], ah[0][3], l0, l1);
                MMA16816(acc[1][2 * bp],     ah[1][0], ah[1][1], ah[1][2], ah[1][3], l0, l1);
                MMA16816(acc[0][2 * bp + 1], ah[0][0], ah[0][1], ah[0][2], ah[0][3], l2, l3);
                MMA16816(acc[1][2 * bp + 1], ah[1][0], ah[1][1], ah[1][2], ah[1][3], l2, l3);
                MMA16816(acc[0][2 * bp],     al[0][0], al[0][1], al[0][2], al[0][3], h0, h1);
                MMA16816(acc[1][2 * bp],     al[1][0], al[1][1], al[1][2], al[1][3], h0, h1);
                MMA16816(acc[0][2 * bp + 1], al[0][0], al[0][1], al[0][2], al[0][3], h2, h3);
                MMA16816(acc[1][2 * bp + 1], al[1][0], al[1][1], al[1][2], al[1][3], h2, h3);
            }
        }
    }

#pragma unroll
    for (int mf = 0; mf < 2; mf++) {
        int r0 = m0 + mw + mf * 16 + (lane >> 2);
        int r1 = r0 + 8;
#pragma unroll
        for (int nf = 0; nf < 8; nf++) {
            float d0 = acc[mf][nf][0], d1 = acc[mf][nf][1];
            float d2 = acc[mf][nf][2], d3 = acc[mf][nf][3];
            int c0 = nw + nf * 8 + (lane & 3) * 2;
            if (mode == 2) {
                int gc = t * 128 + c0;
                float2 bb = *(const float2*)(aux + gc);
                float* dst = (gc < 128) ? (g_h + gc) : (g_c + gc - 128);
                if (r0 < n) {
                    float e0 = d0 + bb.x, e1 = d1 + bb.y;
                    e0 = (e0 > 0.f) ? e0 : expm1f(e0);
                    e1 = (e1 > 0.f) ? e1 : expm1f(e1);
                    float2 o; o.x = e0; o.y = e1;
                    *(float2*)(dst + (size_t)r0 * 128) = o;
                }
                if (r1 < n) {
                    float e0 = d2 + bb.x, e1 = d3 + bb.y;
                    e0 = (e0 > 0.f) ? e0 : expm1f(e0);
                    e1 = (e1 > 0.f) ? e1 : expm1f(e1);
                    float2 o; o.x = e0; o.y = e1;
                    *(float2*)(dst + (size_t)r1 * 128) = o;
                }
            } else {
                int P = t * 128 + c0;
                float bb0 = aux[(P & 3) * 128 + (P >> 2)];
                float bb1 = aux[((P + 1) & 3) * 128 + ((P + 1) >> 2)];
                if (r0 < n) {
                    float2 o; o.x = d0 + bb0; o.y = d1 + bb1;
                    *(float2*)(o512 + (size_t)r0 * 512 + P) = o;
                }
                if (r1 < n) {
                    float2 o; o.x = d2 + bb0; o.y = d3 + bb1;
                    *(float2*)(o512 + (size_t)r1 * 512 + P) = o;
                }
            }
        }
    }
}

// ---------------- host launcher ----------------
extern "C" void kernel_launch(void* const* d_in, const int* in_sizes, int n_in,
                              void* d_out, int out_size) {
    const float* h  = (const float*)d_in[0];
    const float* c  = (const float*)d_in[1];
    const void*  ei = d_in[2];
    const float* ea = (const float*)d_in[3];
    const float* Wi = (const float*)d_in[4];
    const float* bi = (const float*)d_in[5];
    const float* Wc = (const float*)d_in[6];
    const float* bc = (const float*)d_in[7];
    float* out = (float*)d_out;

    int n   = in_sizes[0] / 128;
    int E   = in_sizes[3];
    int seq = out_size / (n * 128);

    static float* p_base = nullptr;
    static float* p_h = nullptr;
    static __nv_bfloat16 *p_Ph, *p_Pl, *p_zh, *p_zl, *p_WTh, *p_WTl, *p_WIh, *p_WIl;
    if (!p_base) {
        cudaGetSymbolAddress((void**)&p_base, g_base);
        cudaGetSymbolAddress((void**)&p_h, g_h);
        cudaGetSymbolAddress((void**)&p_Ph, g_Ph);
        cudaGetSymbolAddress((void**)&p_Pl, g_Pl);
        cudaGetSymbolAddress((void**)&p_zh, g_zh);
        cudaGetSymbolAddress((void**)&p_zl, g_zl);
        cudaGetSymbolAddress((void**)&p_WTh, g_WTh);
        cudaGetSymbolAddress((void**)&p_WTl, g_WTl);
        cudaGetSymbolAddress((void**)&p_WIh, g_WIh);
        cudaGetSymbolAddress((void**)&p_WIl, g_WIl);
        cudaFuncSetAttribute(k_mma, cudaFuncAttributeMaxDynamicSharedMemorySize, 98304);
        cudaFuncSetAttribute(k_mmaS, cudaFuncAttributeMaxDynamicSharedMemorySize, 49152);
    }

    int nb256 = (n + 255) / 256;
    int eb256 = (E + 255) / 256;
    int nb1024 = (n + 1023) / 1024;
    int mtiles = (n + 127) / 128;
    int mt64 = (n + 63) / 64;
    int prop_blocks = (n * 32 + 255) / 256;
    size_t smem_sz = 98304;
    size_t smemS = 49152;

    // ---- graph setup; index-3 launch is a 1-wave k_mmaS PROBE for ncu.
    // Probe reads stale-but-deterministic state; its outputs (g_c rows<7104,
    // out slab 0 rows<7104) are fully overwritten downstream.
    k_init<<<nb256, 256>>>(n);
    k_detect<<<1, 128>>>((const unsigned int*)ei);
    k_build<<<eb256, 256>>>(ei, ea, E);
    k_mmaS<<<dim3(111, 4), 256, smemS>>>(p_base, out, n);   // PROBE
    k_scan1<<<nb1024, 1024>>>(n);        // also computes dinv
    k_scan2<<<1, 32>>>(nb1024);
    k_scan3<<<nb1024, 1024>>>(n);
    k_scatter<<<eb256, 256>>>(ea, E);
    k_split<<<768, 256>>>(Wc, Wi);

    // ---- loop-invariant precompute ----
    k_prop<<<dim3(prop_blocks, 2), 256>>>(h, c, p_Ph, p_Pl, 256, n);
    // init: elu(Phc @ W_init + b_init) -> g_h, g_c
    k_mma<<<dim3(mtiles, 2), 256, smem_sz>>>(p_Ph, p_Pl, 256, p_WIh, p_WIl, 256,
                                             bi, nullptr, n, 2);
    // base_perm = P_h @ Wc[0:128] + b_cell
    k_mma<<<dim3(mtiles, 4), 256, smem_sz>>>(p_Ph, p_Pl, 256, p_WTh, p_WTl, 128,
                                             bc, p_base, n, 0);

    // ---- sequence: h(t) lives in out[t-1] slab ----
    const float* hsrc = p_h;
    for (int tt = 0; tt < seq; tt++) {
        k_prop<<<dim3(prop_blocks, 1), 256>>>(hsrc, nullptr, p_zh, p_zl, 128, n);
        float* odst = out + (long long)tt * n * 128;
        k_mmaS<<<dim3(mt64, 4), 256, smemS>>>(p_base, odst, n);
        hsrc = odst;
    }
}

// round 13
// speedup vs baseline: 1.3565x; 1.1402x over previous
#include <cuda_runtime.h>
#include <cuda_bf16.h>
#include <cuda_fp16.h>
#include <math.h>
#include <stdint.h>

#define MAXN 20000
#define MAXE 320000

// ---------------- device scratch (no allocs allowed) ----------------
__device__ int   g_is64;
__device__ int   g_src[MAXE];
__device__ int   g_dst[MAXE];
__device__ int   g_esrc[MAXE];
__device__ float g_ewn[MAXE];
__device__ float g_deg[MAXN];
__device__ float g_dinv[MAXN];
__device__ int   g_cnt[MAXN];
__device__ int   g_rowptr[MAXN + 1];
__device__ int   g_cursor[MAXN];
__device__ int   g_part[32];
__device__ int   g_off2[32];
__device__ int   g_total;
__device__ float g_base[(long long)MAXN * 512];   // permuted gate layout [r][P], P = hcol*4 + gate
__device__ float g_h[MAXN * 128];
__device__ float g_c[MAXN * 128];
// bf16-split activations (init path)
__device__ __nv_bfloat16 g_Ph[MAXN * 256];   // [P_h | P_c] hi
__device__ __nv_bfloat16 g_Pl[MAXN * 256];   // lo
// fp16-split activations (sequence path)
__device__ __half g_zh[MAXN * 128];
__device__ __half g_zl[MAXN * 128];
// bf16-split transposed weights (init/base), perm P = hcol*4 + gate
__device__ __nv_bfloat16 g_WTh[2 * 512 * 128];
__device__ __nv_bfloat16 g_WTl[2 * 512 * 128];
__device__ __nv_bfloat16 g_WIh[256 * 256];
__device__ __nv_bfloat16 g_WIl[256 * 256];
// fp16 single-precision weights for W_cell m=1 half (sequence path), permuted [P][k]
__device__ __half g_WF[512 * 128];

// ---------------- helpers ----------------
__device__ __forceinline__ float tanhA(float x) {
    float r; asm("tanh.approx.f32 %0, %1;" : "=f"(r) : "f"(x)); return r;
}
__device__ __forceinline__ float sigA(float x) {
    return fmaf(tanhA(0.5f * x), 0.5f, 0.5f);
}
__device__ __forceinline__ uint32_t smem_u32(const void* p) {
    uint32_t a;
    asm("{ .reg .u64 t; cvta.to.shared.u64 t, %1; cvt.u32.u64 %0, t; }" : "=r"(a) : "l"(p));
    return a;
}

#define CP16(dst, src, srcsz) \
    asm volatile("cp.async.ca.shared.global [%0], [%1], 16, %2;" \
        :: "r"(dst), "l"(src), "r"(srcsz))
#define CP_COMMIT() asm volatile("cp.async.commit_group;" ::: "memory")
#define CP_WAIT(nn) asm volatile("cp.async.wait_group %0;" :: "n"(nn) : "memory")

#define LDSM4(r0, r1, r2, r3, a) \
    asm volatile("ldmatrix.sync.aligned.m8n8.x4.shared.b16 {%0,%1,%2,%3}, [%4];" \
        : "=r"(r0), "=r"(r1), "=r"(r2), "=r"(r3) : "r"(a))

#define MMA16816(d, a0, a1, a2, a3, b0, b1) \
    asm volatile("mma.sync.aligned.m16n8k16.row.col.f32.bf16.bf16.f32 " \
        "{%0,%1,%2,%3}, {%4,%5,%6,%7}, {%8,%9}, {%0,%1,%2,%3};" \
        : "+f"((d)[0]), "+f"((d)[1]), "+f"((d)[2]), "+f"((d)[3]) \
        : "r"(a0), "r"(a1), "r"(a2), "r"(a3), "r"(b0), "r"(b1))

#define MMAH(d, a0, a1, a2, a3, b0, b1) \
    asm volatile("mma.sync.aligned.m16n8k16.row.col.f32.f16.f16.f32 " \
        "{%0,%1,%2,%3}, {%4,%5,%6,%7}, {%8,%9}, {%0,%1,%2,%3};" \
        : "+f"((d)[0]), "+f"((d)[1]), "+f"((d)[2]), "+f"((d)[3]) \
        : "r"(a0), "r"(a1), "r"(a2), "r"(a3), "r"(b0), "r"(b1))

// smem swizzle: 64B rows, 4x16B granules, conflict-free for 8-row LDSM phases
__device__ __forceinline__ uint32_t swz(int row, int g) {
    return (uint32_t)(row * 64 + ((g ^ ((row >> 1) & 3)) << 4));
}

// ---------------- setup kernels ----------------
__global__ void k_init(int n) {
    int i = blockIdx.x * blockDim.x + threadIdx.x;
    if (i < n) { g_deg[i] = 0.f; g_cnt[i] = 0; }
    if (i == 0) g_is64 = 1;
}

__global__ void k_detect(const unsigned int* __restrict__ w) {
    unsigned int v = w[2 * threadIdx.x + 1];
    if (v != 0u) g_is64 = 0;
}

__global__ void k_build(const void* __restrict__ ei, const float* __restrict__ ea, int E) {
    int e = blockIdx.x * blockDim.x + threadIdx.x;
    if (e >= E) return;
    int s, d;
    if (g_is64) {
        const long long* p = (const long long*)ei;
        s = (int)p[e]; d = (int)p[E + e];
    } else {
        const int* p = (const int*)ei;
        s = p[e]; d = p[E + e];
    }
    g_src[e] = s; g_dst[e] = d;
    atomicAdd(&g_deg[d], ea[e]);
    atomicAdd(&g_cnt[d], 1);
}

// hierarchical scan pass 1 (+ dinv fused)
__global__ void k_scan1(int n) {
    __shared__ int s[1024];
    int i = blockIdx.x * 1024 + threadIdx.x;
    if (i < n) g_dinv[i] = rsqrtf(g_deg[i] + 1.0f);
    int v = (i < n) ? g_cnt[i] : 0;
    s[threadIdx.x] = v;
    __syncthreads();
    for (int off = 1; off < 1024; off <<= 1) {
        int t = (threadIdx.x >= off) ? s[threadIdx.x - off] : 0;
        __syncthreads();
        s[threadIdx.x] += t;
        __syncthreads();
    }
    if (i < n) g_rowptr[i] = s[threadIdx.x] - v;   // local exclusive
    if (threadIdx.x == 1023) g_part[blockIdx.x] = s[1023];
}

__global__ void k_scan2(int nb) {
    int tid = threadIdx.x;                 // 32 threads
    int v = (tid < nb) ? g_part[tid] : 0;
    int incl = v;
    for (int o = 1; o < 32; o <<= 1) {
        int t = __shfl_up_sync(0xffffffffu, incl, o);
        if (tid >= o) incl += t;
    }
    if (tid < nb) g_off2[tid] = incl - v;
    if (tid == 31) g_total = incl;
}

__global__ void k_scan3(int n) {
    int i = blockIdx.x * 1024 + threadIdx.x;
    if (i < n) {
        int val = g_rowptr[i] + g_off2[blockIdx.x];
        g_rowptr[i] = val;
        g_cursor[i] = val;
    }
    if (i == 0) g_rowptr[n] = g_total;
}

__global__ void k_scatter(const float* __restrict__ ea, int E) {
    int e = blockIdx.x * blockDim.x + threadIdx.x;
    if (e >= E) return;
    int s = g_src[e], d = g_dst[e];
    int pos = atomicAdd(&g_cursor[d], 1);
    g_esrc[pos] = s;
    g_ewn[pos] = g_dinv[s] * ea[e] * g_dinv[d];
}

// fused weight transpose + permute + splits
// ids [0, 131072): W_cell bf16 split; perm P = hcol*4 + q <-> orig col q*128 + hcol
// ids [131072, 196608): W_init bf16 split, transposed [p][k]
// ids [196608, 262144): g_WF fp16 single of W_cell m=1 half, permuted [P][k]
__global__ void k_split(const float* __restrict__ Wc, const float* __restrict__ Wi) {
    int id = blockIdx.x * blockDim.x + threadIdx.x;   // 0 .. 262143
    if (id < 131072) {
        int m = id >> 16;
        int rem = id & 65535;
        int p = rem >> 7;
        int k = rem & 127;
        int hcol = p >> 2, q = p & 3;
        int nc = q * 128 + hcol;
        float v = Wc[(long long)(m * 128 + k) * 512 + nc];
        __nv_bfloat16 hb = __float2bfloat16_rn(v);
        float lf = v - __bfloat162float(hb);
        g_WTh[id] = hb;
        g_WTl[id] = __float2bfloat16_rn(lf);
    } else if (id < 196608) {
        int id2 = id - 131072;
        int p = id2 >> 8;
        int k = id2 & 255;
        float v = Wi[(long long)k * 256 + p];
        __nv_bfloat16 hb = __float2bfloat16_rn(v);
        float lf = v - __bfloat162float(hb);
        g_WIh[id2] = hb;
        g_WIl[id2] = __float2bfloat16_rn(lf);
    } else {
        int id3 = id - 196608;
        int P = id3 >> 7;
        int k = id3 & 127;
        int hcol = P >> 2, q = P & 3;
        float v = Wc[(long long)(128 + k) * 512 + q * 128 + hcol];
        g_WF[id3] = __float2half_rn(v);
    }
}

// ---------------- sparse propagate -> bf16 hi/lo split output (init path) ------
__global__ void k_prop(const float* __restrict__ x0, const float* __restrict__ x1,
                       __nv_bfloat16* __restrict__ oh, __nv_bfloat16* __restrict__ ol,
                       int ldo, int n) {
    const float* x = blockIdx.y ? x1 : x0;
    int coff = blockIdx.y * 128;
    int v = (blockIdx.x * blockDim.x + threadIdx.x) >> 5;
    int lane = threadIdx.x & 31;
    if (v >= n) return;
    int beg = g_rowptr[v], end = g_rowptr[v + 1];
    float ax = 0.f, ay = 0.f, az = 0.f, aw = 0.f;
    int e = beg;
    for (; e + 1 < end; e += 2) {
        int s0 = g_esrc[e], s1 = g_esrc[e + 1];
        float w0 = g_ewn[e], w1 = g_ewn[e + 1];
        float4 v0 = __ldg((const float4*)(x + (long long)s0 * 128) + lane);
        float4 v1 = __ldg((const float4*)(x + (long long)s1 * 128) + lane);
        ax = fmaf(w0, v0.x, ax); ay = fmaf(w0, v0.y, ay);
        az = fmaf(w0, v0.z, az); aw = fmaf(w0, v0.w, aw);
        ax = fmaf(w1, v1.x, ax); ay = fmaf(w1, v1.y, ay);
        az = fmaf(w1, v1.z, az); aw = fmaf(w1, v1.w, aw);
    }
    if (e < end) {
        int s0 = g_esrc[e];
        float w0 = g_ewn[e];
        float4 v0 = __ldg((const float4*)(x + (long long)s0 * 128) + lane);
        ax = fmaf(w0, v0.x, ax); ay = fmaf(w0, v0.y, ay);
        az = fmaf(w0, v0.z, az); aw = fmaf(w0, v0.w, aw);
    }
    float di = g_dinv[v];
    float w2 = di * di;
    float4 vv = __ldg((const float4*)(x + (long long)v * 128) + lane);
    ax = fmaf(w2, vv.x, ax); ay = fmaf(w2, vv.y, ay);
    az = fmaf(w2, vv.z, az); aw = fmaf(w2, vv.w, aw);
    float a[4] = {ax, ay, az, aw};
    unsigned short hs[4], ls[4];
#pragma unroll
    for (int m = 0; m < 4; m++) {
        __nv_bfloat16 hb = __float2bfloat16_rn(a[m]);
        float lf = a[m] - __bfloat162float(hb);
        __nv_bfloat16 lb = __float2bfloat16_rn(lf);
        hs[m] = *(unsigned short*)&hb;
        ls[m] = *(unsigned short*)&lb;
    }
    *(uint2*)(oh + (long long)v * ldo + coff + lane * 4) = *(uint2*)hs;
    *(uint2*)(ol + (long long)v * ldo + coff + lane * 4) = *(uint2*)ls;
}

// ---------------- sparse propagate -> fp16 hi/lo split output (sequence path) ----
__global__ void k_prop16(const float* __restrict__ x, int n) {
    int v = (blockIdx.x * blockDim.x + threadIdx.x) >> 5;
    int lane = threadIdx.x & 31;
    if (v >= n) return;
    int beg = g_rowptr[v], end = g_rowptr[v + 1];
    float ax = 0.f, ay = 0.f, az = 0.f, aw = 0.f;
    int e = beg;
    for (; e + 1 < end; e += 2) {
        int s0 = g_esrc[e], s1 = g_esrc[e + 1];
        float w0 = g_ewn[e], w1 = g_ewn[e + 1];
        float4 v0 = __ldg((const float4*)(x + (long long)s0 * 128) + lane);
        float4 v1 = __ldg((const float4*)(x + (long long)s1 * 128) + lane);
        ax = fmaf(w0, v0.x, ax); ay = fmaf(w0, v0.y, ay);
        az = fmaf(w0, v0.z, az); aw = fmaf(w0, v0.w, aw);
        ax = fmaf(w1, v1.x, ax); ay = fmaf(w1, v1.y, ay);
        az = fmaf(w1, v1.z, az); aw = fmaf(w1, v1.w, aw);
    }
    if (e < end) {
        int s0 = g_esrc[e];
        float w0 = g_ewn[e];
        float4 v0 = __ldg((const float4*)(x + (long long)s0 * 128) + lane);
        ax = fmaf(w0, v0.x, ax); ay = fmaf(w0, v0.y, ay);
        az = fmaf(w0, v0.z, az); aw = fmaf(w0, v0.w, aw);
    }
    float di = g_dinv[v];
    float w2 = di * di;
    float4 vv = __ldg((const float4*)(x + (long long)v * 128) + lane);
    ax = fmaf(w2, vv.x, ax); ay = fmaf(w2, vv.y, ay);
    az = fmaf(w2, vv.z, az); aw = fmaf(w2, vv.w, aw);
    float a[4] = {ax, ay, az, aw};
    unsigned short hs[4], ls[4];
#pragma unroll
    for (int m = 0; m < 4; m++) {
        __half hb = __float2half_rn(a[m]);
        float lf = a[m] - __half2float(hb);
        __half lb = __float2half_rn(lf);
        hs[m] = *(unsigned short*)&hb;
        ls[m] = *(unsigned short*)&lb;
    }
    *(uint2*)(g_zh + (long long)v * 128 + lane * 4) = *(uint2*)hs;
    *(uint2*)(g_zl + (long long)v * 128 + lane * 4) = *(uint2*)ls;
}

// ---------------- sequence GEMM: fp16 2-term, M64 x N128 tile ----------------
// D = (Xh + Xl) @ W^T ; X fp16 hi/lo (22-bit activation), W single fp16.
// smem per 16KB stage: Ah[0,4K) Al[4K,8K) W[8K,16K); 64B swizzled rows; 2 stages.
// gates = D + base_perm; LSTM update g_c; write oseq.
__global__ void __launch_bounds__(256, 3)
k_mmaS(const float* __restrict__ baseb, float* __restrict__ oseq, int n) {
    extern __shared__ char sm[];
    const uint32_t sb = smem_u32(sm);
    const int tid = threadIdx.x;
    const int lane = tid & 31;
    const int wid = tid >> 5;
    const int m0 = blockIdx.x * 64;
    const int t = blockIdx.y;
    const int mw = (wid & 1) * 32;
    const int nw = (wid >> 1) * 32;

    float acc[2][4][4];
#pragma unroll
    for (int i = 0; i < 2; i++)
#pragma unroll
        for (int j = 0; j < 4; j++)
#pragma unroll
            for (int q = 0; q < 4; q++) acc[i][j][q] = 0.f;

    auto stage = [&](int ks) {
        uint32_t bufo = (uint32_t)(ks & 1) * 16384;
#pragma unroll
        for (int it = 0; it < 4; it++) {
            int id = tid + it * 256;        // 0..1023
            if (id < 512) {
                int arr = id >> 8;          // 0:Ah 1:Al
                int rem = id & 255;
                int row = rem >> 2, g = rem & 3;
                uint32_t dst = sb + bufo + arr * 4096 + swz(row, g);
                const __half* src = (arr == 0 ? g_zh : g_zl)
                    + (size_t)(m0 + row) * 128 + ks * 32 + g * 8;
                int ok = (m0 + row < n) ? 16 : 0;
                CP16(dst, src, ok);
            } else {
                int rem = id - 512;         // 0..511
                int row = rem >> 2, g = rem & 3;
                uint32_t dst = sb + bufo + 8192 + swz(row, g);
                const __half* src = g_WF
                    + (size_t)(t * 128 + row) * 128 + ks * 32 + g * 8;
                CP16(dst, src, 16);
            }
        }
        CP_COMMIT();
    };

    stage(0);
#pragma unroll
    for (int ks = 0; ks < 4; ks++) {
        if (ks + 1 < 4) { stage(ks + 1); CP_WAIT(1); } else { CP_WAIT(0); }
        __syncthreads();
        uint32_t abase = sb + (uint32_t)(ks & 1) * 16384;
        uint32_t bbase = abase + 8192;
#pragma unroll
        for (int kc = 0; kc < 2; kc++) {
            uint32_t ah[2][4], al[2][4];
#pragma unroll
            for (int mf = 0; mf < 2; mf++) {
                int row = mw + mf * 16 + (lane & 15);
                int g = kc * 2 + (lane >> 4);
                uint32_t a = abase + swz(row, g);
                LDSM4(ah[mf][0], ah[mf][1], ah[mf][2], ah[mf][3], a);
                LDSM4(al[mf][0], al[mf][1], al[mf][2], al[mf][3], a + 4096);
            }
            uint32_t wf[2][4];
#pragma unroll
            for (int bp = 0; bp < 2; bp++) {
                int p = nw + bp * 16 + ((lane >> 4) << 3) + (lane & 7);
                int g = kc * 2 + ((lane >> 3) & 1);
                uint32_t a = bbase + swz(p, g);
                LDSM4(wf[bp][0], wf[bp][1], wf[bp][2], wf[bp][3], a);
            }
            // 16 MMAs: Xh term then Xl term (reuse distance 8)
#pragma unroll
            for (int bp = 0; bp < 2; bp++) {
                MMAH(acc[0][2 * bp],     ah[0][0], ah[0][1], ah[0][2], ah[0][3], wf[bp][0], wf[bp][1]);
                MMAH(acc[1][2 * bp],     ah[1][0], ah[1][1], ah[1][2], ah[1][3], wf[bp][0], wf[bp][1]);
                MMAH(acc[0][2 * bp + 1], ah[0][0], ah[0][1], ah[0][2], ah[0][3], wf[bp][2], wf[bp][3]);
                MMAH(acc[1][2 * bp + 1], ah[1][0], ah[1][1], ah[1][2], ah[1][3], wf[bp][2], wf[bp][3]);
            }
#pragma unroll
            for (int bp = 0; bp < 2; bp++) {
                MMAH(acc[0][2 * bp],     al[0][0], al[0][1], al[0][2], al[0][3], wf[bp][0], wf[bp][1]);
                MMAH(acc[1][2 * bp],     al[1][0], al[1][1], al[1][2], al[1][3], wf[bp][0], wf[bp][1]);
                MMAH(acc[0][2 * bp + 1], al[0][0], al[0][1], al[0][2], al[0][3], wf[bp][2], wf[bp][3]);
                MMAH(acc[1][2 * bp + 1], al[1][0], al[1][1], al[1][2], al[1][3], wf[bp][2], wf[bp][3]);
            }
        }
        __syncthreads();
    }

    // ---- LSTM epilogue ----
#pragma unroll
    for (int mf = 0; mf < 2; mf++) {
        int r0 = m0 + mw + mf * 16 + (lane >> 2);
        int r1 = r0 + 8;
#pragma unroll
        for (int nf = 0; nf < 4; nf++) {
            float d0 = acc[mf][nf][0], d1 = acc[mf][nf][1];
            float d2 = acc[mf][nf][2], d3 = acc[mf][nf][3];
            int c0 = nw + nf * 8 + (lane & 3) * 2;
            int P0 = t * 128 + c0;
            float2 b0 = make_float2(0.f, 0.f), b1 = make_float2(0.f, 0.f);
            if (r0 < n) b0 = *(const float2*)(baseb + (size_t)r0 * 512 + P0);
            if (r1 < n) b1 = *(const float2*)(baseb + (size_t)r1 * 512 + P0);
            float v0 = d0 + b0.x, v1 = d1 + b0.y;
            float v2 = d2 + b1.x, v3 = d3 + b1.y;
            float u0 = __shfl_xor_sync(0xffffffffu, v0, 1);
            float u1 = __shfl_xor_sync(0xffffffffu, v1, 1);
            float u2 = __shfl_xor_sync(0xffffffffu, v2, 1);
            float u3 = __shfl_xor_sync(0xffffffffu, v3, 1);
            if (!(lane & 1)) {
                // this lane: (i, f); partner: (o, g)
                int hcol = P0 >> 2;
                if (r0 < n) {
                    size_t ix = (size_t)r0 * 128 + hcol;
                    float cold = g_c[ix];
                    float cn = sigA(v1) * cold + sigA(v0) * tanhA(u1);
                    float hn = sigA(u0) * tanhA(cn);
                    g_c[ix] = cn; oseq[ix] = hn;
                }
                if (r1 < n) {
                    size_t ix = (size_t)r1 * 128 + hcol;
                    float cold = g_c[ix];
                    float cn = sigA(v3) * cold + sigA(v2) * tanhA(u3);
                    float hn = sigA(u2) * tanhA(cn);
                    g_c[ix] = cn; oseq[ix] = hn;
                }
            }
        }
    }
}

// ---------------- bf16 split-3 tensor GEMM (init + base precompute) ----------------
// mode 0: o512[r*512 + P] = D + bc[orig col]   (permuted base precompute)
// mode 2: init: elu(D + bi[col]) -> g_h (cols<128) / g_c
__global__ void __launch_bounds__(256, 2)
k_mma(const __nv_bfloat16* __restrict__ Ah, const __nv_bfloat16* __restrict__ Al, int lda,
      const __nv_bfloat16* __restrict__ Bh, const __nv_bfloat16* __restrict__ Bl,
      int K, const float* __restrict__ aux, float* __restrict__ o512, int n, int mode) {
    extern __shared__ char sm[];
    const uint32_t sb = smem_u32(sm);
    const int tid = threadIdx.x;
    const int lane = tid & 31;
    const int wid = tid >> 5;
    const int m0 = blockIdx.x * 128;
    const int t = blockIdx.y;
    const int mw = (wid & 3) * 32;
    const int nw = (wid >> 2) * 64;

    float acc[2][8][4];
#pragma unroll
    for (int i = 0; i < 2; i++)
#pragma unroll
        for (int j = 0; j < 8; j++)
#pragma unroll
            for (int q = 0; q < 4; q++) acc[i][j][q] = 0.f;

    const int nslab = K >> 5;

    auto stage = [&](int ks) {
        uint32_t bufo = (uint32_t)(ks % 3) * 32768;
#pragma unroll
        for (int it = 0; it < 8; it++) {
            int id = tid + it * 256;
            int arr = id >> 9;
            int rem = id & 511;
            int row = rem >> 2, g = rem & 3;
            uint32_t dst = sb + bufo + arr * 8192 + swz(row, g);
            if (arr < 2) {
                const __nv_bfloat16* src = (arr == 0 ? Ah : Al)
                    + (size_t)(m0 + row) * lda + ks * 32 + g * 8;
                int ok = (m0 + row < n) ? 16 : 0;
                CP16(dst, src, ok);
            } else {
                const __nv_bfloat16* src = (arr == 2 ? Bh : Bl)
                    + (size_t)(t * 128 + row) * K + ks * 32 + g * 8;
                CP16(dst, src, 16);
            }
        }
        CP_COMMIT();
    };

    stage(0);
    stage(1);
    for (int ks = 0; ks < nslab; ks++) {
        if (ks == nslab - 1) { CP_WAIT(0); } else { CP_WAIT(1); }
        __syncthreads();
        if (ks + 2 < nslab) stage(ks + 2);
        uint32_t abase = sb + (uint32_t)(ks % 3) * 32768;
        uint32_t bbase = abase + 16384;
#pragma unroll
        for (int kc = 0; kc < 2; kc++) {
            uint32_t ah[2][4], al[2][4];
#pragma unroll
            for (int mf = 0; mf < 2; mf++) {
                int row = mw + mf * 16 + (lane & 15);
                int g = kc * 2 + (lane >> 4);
                uint32_t a = abase + swz(row, g);
                LDSM4(ah[mf][0], ah[mf][1], ah[mf][2], ah[mf][3], a);
                LDSM4(al[mf][0], al[mf][1], al[mf][2], al[mf][3], a + 8192);
            }
#pragma unroll
            for (int bp = 0; bp < 4; bp++) {
                int p = nw + bp * 16 + ((lane >> 4) << 3) + (lane & 7);
                int g = kc * 2 + ((lane >> 3) & 1);
                uint32_t a = bbase + swz(p, g);
                uint32_t h0, h1, h2, h3, l0, l1, l2, l3;
                LDSM4(h0, h1, h2, h3, a);
                LDSM4(l0, l1, l2, l3, a + 8192);
                MMA16816(acc[0][2 * bp],     ah[0][0], ah[0][1], ah[0][2], ah[0][3], h0, h1);
                MMA16816(acc[1][2 * bp],     ah[1][0], ah[1][1], ah[1][2], ah[1][3], h0, h1);
                MMA16816(acc[0][2 * bp + 1], ah[0][0], ah[0][1], ah[0][2], ah[0][3], h2, h3);
                MMA16816(acc[1][2 * bp + 1], ah[1][0], ah[1][1], ah[1][2], ah[1][3], h2, h3);
                MMA16816(acc[0][2 * bp],     ah[0][0], ah[0][1], ah[0][2], ah[0][3], l0, l1);
                MMA16816(acc[1][2 * bp],     ah[1][0], ah[1][1], ah[1][2], ah[1][3], l0, l1);
                MMA16816(acc[0][2 * bp + 1], ah[0][0], ah[0][1], ah[0][2], ah[0][3], l2, l3);
                MMA16816(acc[1][2 * bp + 1], ah[1][0], ah[1][1], ah[1][2], ah[1][3], l2, l3);
                MMA16816(acc[0][2 * bp],     al[0][0], al[0][1], al[0][2], al[0][3], h0, h1);
                MMA16816(acc[1][2 * bp],     al[1][0], al[1][1], al[1][2], al[1][3], h0, h1);
                MMA16816(acc[0][2 * bp + 1], al[0][0], al[0][1], al[0][2], al[0][3], h2, h3);
                MMA16816(acc[1][2 * bp + 1], al[1][0], al[1][1], al[1][2], al[1][3], h2, h3);
            }
        }
    }

#pragma unroll
    for (int mf = 0; mf < 2; mf++) {
        int r0 = m0 + mw + mf * 16 + (lane >> 2);
        int r1 = r0 + 8;
#pragma unroll
        for (int nf = 0; nf < 8; nf++) {
            float d0 = acc[mf][nf][0], d1 = acc[mf][nf][1];
            float d2 = acc[mf][nf][2], d3 = acc[mf][nf][3];
            int c0 = nw + nf * 8 + (lane & 3) * 2;
            if (mode == 2) {
                int gc = t * 128 + c0;
                float2 bb = *(const float2*)(aux + gc);
                float* dst = (gc < 128) ? (g_h + gc) : (g_c + gc - 128);
                if (r0 < n) {
                    float e0 = d0 + bb.x, e1 = d1 + bb.y;
                    e0 = (e0 > 0.f) ? e0 : expm1f(e0);
                    e1 = (e1 > 0.f) ? e1 : expm1f(e1);
                    float2 o; o.x = e0; o.y = e1;
                    *(float2*)(dst + (size_t)r0 * 128) = o;
                }
                if (r1 < n) {
                    float e0 = d2 + bb.x, e1 = d3 + bb.y;
                    e0 = (e0 > 0.f) ? e0 : expm1f(e0);
                    e1 = (e1 > 0.f) ? e1 : expm1f(e1);
                    float2 o; o.x = e0; o.y = e1;
                    *(float2*)(dst + (size_t)r1 * 128) = o;
                }
            } else {
                int P = t * 128 + c0;
                float bb0 = aux[(P & 3) * 128 + (P >> 2)];
                float bb1 = aux[((P + 1) & 3) * 128 + ((P + 1) >> 2)];
                if (r0 < n) {
                    float2 o; o.x = d0 + bb0; o.y = d1 + bb1;
                    *(float2*)(o512 + (size_t)r0 * 512 + P) = o;
                }
                if (r1 < n) {
                    float2 o; o.x = d2 + bb0; o.y = d3 + bb1;
                    *(float2*)(o512 + (size_t)r1 * 512 + P) = o;
                }
            }
        }
    }
}

// ---------------- host launcher ----------------
extern "C" void kernel_launch(void* const* d_in, const int* in_sizes, int n_in,
                              void* d_out, int out_size) {
    const float* h  = (const float*)d_in[0];
    const float* c  = (const float*)d_in[1];
    const void*  ei = d_in[2];
    const float* ea = (const float*)d_in[3];
    const float* Wi = (const float*)d_in[4];
    const float* bi = (const float*)d_in[5];
    const float* Wc = (const float*)d_in[6];
    const float* bc = (const float*)d_in[7];
    float* out = (float*)d_out;

    int n   = in_sizes[0] / 128;
    int E   = in_sizes[3];
    int seq = out_size / (n * 128);

    static float* p_base = nullptr;
    static float* p_h = nullptr;
    static __nv_bfloat16 *p_Ph, *p_Pl, *p_WTh, *p_WTl, *p_WIh, *p_WIl;
    if (!p_base) {
        cudaGetSymbolAddress((void**)&p_base, g_base);
        cudaGetSymbolAddress((void**)&p_h, g_h);
        cudaGetSymbolAddress((void**)&p_Ph, g_Ph);
        cudaGetSymbolAddress((void**)&p_Pl, g_Pl);
        cudaGetSymbolAddress((void**)&p_WTh, g_WTh);
        cudaGetSymbolAddress((void**)&p_WTl, g_WTl);
        cudaGetSymbolAddress((void**)&p_WIh, g_WIh);
        cudaGetSymbolAddress((void**)&p_WIl, g_WIl);
        cudaFuncSetAttribute(k_mma, cudaFuncAttributeMaxDynamicSharedMemorySize, 98304);
        cudaFuncSetAttribute(k_mmaS, cudaFuncAttributeMaxDynamicSharedMemorySize, 32768);
    }

    int nb256 = (n + 255) / 256;
    int eb256 = (E + 255) / 256;
    int nb1024 = (n + 1023) / 1024;
    int mtiles = (n + 127) / 128;
    int mt64 = (n + 63) / 64;
    int prop_blocks = (n * 32 + 255) / 256;
    size_t smem_sz = 98304;
    size_t smemS = 32768;

    // ---- graph setup (per launch; deterministic) ----
    k_init<<<nb256, 256>>>(n);
    k_detect<<<1, 128>>>((const unsigned int*)ei);
    k_build<<<eb256, 256>>>(ei, ea, E);
    k_scan1<<<nb1024, 1024>>>(n);        // also computes dinv
    k_scan2<<<1, 32>>>(nb1024);
    k_scan3<<<nb1024, 1024>>>(n);
    k_scatter<<<eb256, 256>>>(ea, E);
    k_split<<<1024, 256>>>(Wc, Wi);

    // ---- loop-invariant precompute ----
    k_prop<<<dim3(prop_blocks, 2), 256>>>(h, c, p_Ph, p_Pl, 256, n);
    // init: elu(Phc @ W_init + b_init) -> g_h, g_c
    k_mma<<<dim3(mtiles, 2), 256, smem_sz>>>(p_Ph, p_Pl, 256, p_WIh, p_WIl, 256,
                                             bi, nullptr, n, 2);
    // base_perm = P_h @ Wc[0:128] + b_cell
    k_mma<<<dim3(mtiles, 4), 256, smem_sz>>>(p_Ph, p_Pl, 256, p_WTh, p_WTl, 128,
                                             bc, p_base, n, 0);

    // ---- sequence: h(t) lives in out[t-1] slab ----
    const float* hsrc = p_h;
    for (int tt = 0; tt < seq; tt++) {
        k_prop16<<<prop_blocks, 256>>>(hsrc, n);
        float* odst = out + (long long)tt * n * 128;
        k_mmaS<<<dim3(mt64, 4), 256, smemS>>>(p_base, odst, n);
        hsrc = odst;
    }
}